// round 15
// baseline (speedup 1.0000x reference)
#include <cuda_runtime.h>
#include <cuda_fp16.h>
#include <cstdint>

#define KC      32              // k elems per chunk
#define NCH     16              // 512 / 32
#define MT      64              // rows per CTA
#define NTHR    512
#define STR     80              // smem row stride bytes (32 fp16 = 64B + 16 pad)
#define AH_OFF  0               // A hi: 64*80 = 5120
#define AL_OFF  5120            // A lo: 64*80 = 5120
#define BH_OFF  10240           // B hi: 512*80 = 40960
#define STG_SZ  51200
#define STAGE0  6144            // after b1/gamma/beta (1536 floats)
#define SMEM_TOTAL (STAGE0 + 2 * STG_SZ)

__device__ unsigned short g_W1h[512 * 512];

__global__ void split_w_kernel(const float* __restrict__ W1) {
    int i = blockIdx.x * 256 + threadIdx.x;
    g_W1h[i] = __half_as_ushort(__float2half_rn(W1[i]));
}

__device__ __forceinline__ uint32_t smem_u32(const void* p) {
    uint32_t a;
    asm("{ .reg .u64 t; cvta.to.shared.u64 t, %1; cvt.u32.u64 %0, t; }" : "=r"(a) : "l"(p));
    return a;
}
__device__ __forceinline__ void ldsm4(uint32_t* r, uint32_t a) {
    asm volatile("ldmatrix.sync.aligned.m8n8.x4.shared.b16 {%0,%1,%2,%3}, [%4];"
                 : "=r"(r[0]), "=r"(r[1]), "=r"(r[2]), "=r"(r[3]) : "r"(a));
}
__device__ __forceinline__ void mma16816(float* c, const uint32_t* a, const uint32_t* b) {
    asm volatile("mma.sync.aligned.m16n8k16.row.col.f32.f16.f16.f32 "
                 "{%0,%1,%2,%3}, {%4,%5,%6,%7}, {%8,%9}, {%0,%1,%2,%3};"
                 : "+f"(c[0]), "+f"(c[1]), "+f"(c[2]), "+f"(c[3])
                 : "r"(a[0]), "r"(a[1]), "r"(a[2]), "r"(a[3]), "r"(b[0]), "r"(b[1]));
}
__device__ __forceinline__ void cp16(uint32_t dst, const void* src) {
    asm volatile("cp.async.ca.shared.global [%0], [%1], 16;"
                 :: "r"(dst), "l"(__cvta_generic_to_global(src)));
}
// split 4 floats into fp16 hi pair + fp16 lo pair
__device__ __forceinline__ void cv4(const float4& v, uint32_t* hi, uint32_t* lo) {
    float w[4] = {v.x, v.y, v.z, v.w};
#pragma unroll
    for (int e = 0; e < 2; ++e) {
        __half h0 = __float2half_rn(w[2*e]);
        __half h1 = __float2half_rn(w[2*e+1]);
        __half l0 = __float2half_rn(w[2*e]   - __half2float(h0));
        __half l1 = __float2half_rn(w[2*e+1] - __half2float(h1));
        hi[e] = ((uint32_t)__half_as_ushort(h1) << 16) | __half_as_ushort(h0);
        lo[e] = ((uint32_t)__half_as_ushort(l1) << 16) | __half_as_ushort(l0);
    }
}

__global__ void __launch_bounds__(NTHR, 1)
hmma_head(const float* __restrict__ x,  const float* __restrict__ b1,
          const float* __restrict__ gamma, const float* __restrict__ beta,
          const float* __restrict__ Wout, const float* __restrict__ bout,
          float* __restrict__ out) {
    extern __shared__ char sm[];
    const uint32_t sbase = smem_u32(sm);
    const int tid  = threadIdx.x;
    const int lane = tid & 31;
    const int wid  = tid >> 5;         // 0..15
    const int wm   = wid & 3;          // 4 M-warps (16 rows each)
    const int wn   = wid >> 2;         // 4 N-warps (128 cols each)
    const int rowbase = blockIdx.x * MT;

    float* bgb = (float*)sm;           // b1[512] gamma[512] beta[512]
    for (int i = tid; i < 512; i += NTHR) {
        bgb[i]        = b1[i];
        bgb[512 + i]  = gamma[i];
        bgb[1024 + i] = beta[i];
    }

    // A-load duty: row ar (64 rows, 8 threads/row), 4-float quarter aq
    const int ar = tid >> 3, aq = tid & 7;
    const int arg = rowbase + ar;
    const float* xrow = x + (((size_t)((arg >> 9) * 513 + (arg & 511))) << 9) + aq * 4;

    // ---- prologue: chunk 0 into stage 0 ----
    {
        float4 xa = *(const float4*)(xrow);
        uint32_t hi[2], lo[2];
        cv4(xa, hi, lo);
        *(uint2*)(sm + STAGE0 + AH_OFF + ar * STR + aq * 8) = *(uint2*)hi;
        *(uint2*)(sm + STAGE0 + AL_OFF + ar * STR + aq * 8) = *(uint2*)lo;
#pragma unroll
        for (int it = 0; it < 4; ++it) {
            int idx = tid + it * NTHR;
            int row = idx >> 2, q = idx & 3;
            cp16(sbase + STAGE0 + BH_OFF + row * STR + q * 16, g_W1h + row * 512 + q * 8);
        }
        asm volatile("cp.async.commit_group;");
        asm volatile("cp.async.wait_group 0;");
        __syncthreads();
    }

    float acc[16][4];
#pragma unroll
    for (int j = 0; j < 16; ++j)
#pragma unroll
        for (int e = 0; e < 4; ++e) acc[j][e] = 0.f;

    const uint32_t aoff  = (uint32_t)((lane & 15) * STR + (lane >> 4) * 16) + wm * 16 * STR;
    // B ldsm4: m0/m1 = n-rows 0-7 (k0-7, k8-15); m2/m3 = n-rows 8-15
    const uint32_t b4off = (uint32_t)((lane & 7) * STR + ((lane >> 3) & 1) * 16
                                      + (lane >> 4) * 8 * STR) + wn * 128 * STR;

#pragma unroll 1
    for (int c = 0; c < NCH; ++c) {
        const uint32_t stg  = STAGE0 + (uint32_t)(c & 1) * STG_SZ;
        const uint32_t nstg = STAGE0 + (uint32_t)((c & 1) ^ 1) * STG_SZ;
        float4 nxa;
        if (c < NCH - 1) {
            const int k0n = (c + 1) * KC;
            nxa = *(const float4*)(xrow + k0n);
#pragma unroll
            for (int it = 0; it < 4; ++it) {
                int idx = tid + it * NTHR;
                int row = idx >> 2, q = idx & 3;
                cp16(sbase + nstg + BH_OFF + row * STR + q * 16,
                     g_W1h + row * 512 + k0n + q * 8);
            }
            asm volatile("cp.async.commit_group;");
        }

        // ---- compute on stg ----
#pragma unroll
        for (int ks = 0; ks < 2; ++ks) {
            uint32_t ah[4], al[4];
            const uint32_t ab = sbase + stg + aoff + ks * 32;
            ldsm4(ah, ab + AH_OFF);
            ldsm4(al, ab + AL_OFF);

            const uint32_t bb = sbase + stg + b4off + ks * 32 + BH_OFF;
            uint32_t bf[2][4];

            // pass 0: xh * Wh
            ldsm4(bf[0], bb);
#pragma unroll
            for (int jj = 0; jj < 8; ++jj) {
                const int cur = jj & 1, nxt = cur ^ 1;
                if (jj < 7) ldsm4(bf[nxt], bb + (uint32_t)(jj + 1) * (16 * STR));
                mma16816(acc[2*jj],   ah, &bf[cur][0]);
                mma16816(acc[2*jj+1], ah, &bf[cur][2]);
            }
            // pass 1: xl * Wh
            ldsm4(bf[0], bb);
#pragma unroll
            for (int jj = 0; jj < 8; ++jj) {
                const int cur = jj & 1, nxt = cur ^ 1;
                if (jj < 7) ldsm4(bf[nxt], bb + (uint32_t)(jj + 1) * (16 * STR));
                mma16816(acc[2*jj],   al, &bf[cur][0]);
                mma16816(acc[2*jj+1], al, &bf[cur][2]);
            }
        }

        if (c < NCH - 1) {
            uint32_t hi[2], lo[2];
            cv4(nxa, hi, lo);
            *(uint2*)(sm + nstg + AH_OFF + ar * STR + aq * 8) = *(uint2*)hi;
            *(uint2*)(sm + nstg + AL_OFF + ar * STR + aq * 8) = *(uint2*)lo;
        }
        asm volatile("cp.async.wait_group 0;");
        __syncthreads();
    }

    // ---- fused epilogue ----
    float2* stats = (float2*)(sm + STAGE0);          // [4][64]
    float2* munrs = (float2*)(sm + STAGE0 + 2048);   // [64]
    float*  pp    = (float*)(sm + STAGE0 + 2560);    // [4][64]

    // rows this warp covers: r = wm*16 + half*8 + (lane>>2)
#pragma unroll
    for (int half = 0; half < 2; ++half) {
        float s = 0.f, ss = 0.f;
#pragma unroll
        for (int j = 0; j < 16; ++j) {
            const int cc = wn * 128 + j * 8 + (lane & 3) * 2;
            float h0 = acc[j][half * 2 + 0] + bgb[cc];
            float h1 = acc[j][half * 2 + 1] + bgb[cc + 1];
            s += h0 + h1;
            ss += h0 * h0 + h1 * h1;
        }
        s  += __shfl_xor_sync(0xffffffffu, s, 1);  s  += __shfl_xor_sync(0xffffffffu, s, 2);
        ss += __shfl_xor_sync(0xffffffffu, ss, 1); ss += __shfl_xor_sync(0xffffffffu, ss, 2);
        if ((lane & 3) == 0) {
            const int r = wm * 16 + half * 8 + (lane >> 2);
            stats[wn * 64 + r] = make_float2(s, ss);
        }
    }
    __syncthreads();
    if (tid < 64) {
        float s = 0.f, ss = 0.f;
#pragma unroll
        for (int w = 0; w < 4; ++w) { float2 v = stats[w * 64 + tid]; s += v.x; ss += v.y; }
        const float mu = s * (1.f / 512.f);
        const float var = ss * (1.f / 512.f) - mu * mu;
        munrs[tid] = make_float2(mu, rsqrtf(var + 1e-5f));
    }
    __syncthreads();

#pragma unroll
    for (int half = 0; half < 2; ++half) {
        const int r = wm * 16 + half * 8 + (lane >> 2);
        const float2 mr = munrs[r];
        const int tt = (rowbase + r) & 511;
        const float* wrow = Wout + (((size_t)tt) << 9);
        float p = 0.f;
#pragma unroll
        for (int j = 0; j < 16; ++j) {
            const int cc = wn * 128 + j * 8 + (lane & 3) * 2;
            const float2 wo = *(const float2*)(wrow + cc);
            float h0 = acc[j][half * 2 + 0] + bgb[cc];
            float h1 = acc[j][half * 2 + 1] + bgb[cc + 1];
            float y0 = fmaxf((h0 - mr.x) * mr.y * bgb[512 + cc]     + bgb[1024 + cc],     0.f);
            float y1 = fmaxf((h1 - mr.x) * mr.y * bgb[512 + cc + 1] + bgb[1024 + cc + 1], 0.f);
            p += y0 * wo.x + y1 * wo.y;
        }
        p += __shfl_xor_sync(0xffffffffu, p, 1);
        p += __shfl_xor_sync(0xffffffffu, p, 2);
        if ((lane & 3) == 0) pp[wn * 64 + r] = p;
    }
    __syncthreads();
    if (tid < 64) {
        const int rg = rowbase + tid;
        const int tt = rg & 511;
        out[rg] = pp[tid] + pp[64 + tid] + pp[128 + tid] + pp[192 + tid] + bout[tt];
    }
}

extern "C" void kernel_launch(void* const* d_in, const int* in_sizes, int n_in,
                              void* d_out, int out_size) {
    const float* x     = (const float*)d_in[0];
    const float* W1    = (const float*)d_in[1];
    const float* b1    = (const float*)d_in[2];
    const float* gamma = (const float*)d_in[3];
    const float* beta  = (const float*)d_in[4];
    const float* Wout  = (const float*)d_in[5];
    const float* bout  = (const float*)d_in[6];
    float* out = (float*)d_out;

    cudaFuncSetAttribute(hmma_head, cudaFuncAttributeMaxDynamicSharedMemorySize, SMEM_TOTAL);

    split_w_kernel<<<1024, 256>>>(W1);
    hmma_head<<<131072 / MT, NTHR, SMEM_TOTAL>>>(x, b1, gamma, beta, Wout, bout, out);
}

// round 16
// speedup vs baseline: 1.2385x; 1.2385x over previous
#include <cuda_runtime.h>
#include <cuda_fp16.h>
#include <cstdint>

#define KC      32              // k elems per chunk
#define NCH     16              // 512 / 32
#define MT      64              // rows per CTA
#define NTHR    512
#define STR     80              // smem row stride bytes (32 fp16 = 64B + 16 pad)
#define AH_OFF  0               // A: 64*80 = 5120
#define BH_OFF  5120            // B: 512*80 = 40960
#define STG_SZ  46080
#define STAGE0  6144            // after b1/gamma/beta (1536 floats)
#define SMEM_TOTAL (STAGE0 + 2 * STG_SZ)

__device__ unsigned short g_W1h[512 * 512];

__global__ void split_w_kernel(const float* __restrict__ W1) {
    int i = blockIdx.x * 256 + threadIdx.x;
    g_W1h[i] = __half_as_ushort(__float2half_rn(W1[i]));
}

__device__ __forceinline__ uint32_t smem_u32(const void* p) {
    uint32_t a;
    asm("{ .reg .u64 t; cvta.to.shared.u64 t, %1; cvt.u32.u64 %0, t; }" : "=r"(a) : "l"(p));
    return a;
}
__device__ __forceinline__ void ldsm4(uint32_t* r, uint32_t a) {
    asm volatile("ldmatrix.sync.aligned.m8n8.x4.shared.b16 {%0,%1,%2,%3}, [%4];"
                 : "=r"(r[0]), "=r"(r[1]), "=r"(r[2]), "=r"(r[3]) : "r"(a));
}
__device__ __forceinline__ void mma16816(float* c, const uint32_t* a, const uint32_t* b) {
    asm volatile("mma.sync.aligned.m16n8k16.row.col.f32.f16.f16.f32 "
                 "{%0,%1,%2,%3}, {%4,%5,%6,%7}, {%8,%9}, {%0,%1,%2,%3};"
                 : "+f"(c[0]), "+f"(c[1]), "+f"(c[2]), "+f"(c[3])
                 : "r"(a[0]), "r"(a[1]), "r"(a[2]), "r"(a[3]), "r"(b[0]), "r"(b[1]));
}
__device__ __forceinline__ void cp16(uint32_t dst, const void* src) {
    asm volatile("cp.async.ca.shared.global [%0], [%1], 16;"
                 :: "r"(dst), "l"(__cvta_generic_to_global(src)));
}
// convert 4 floats to 2 packed fp16 pairs
__device__ __forceinline__ void cvh4(const float4& v, uint32_t* hi) {
    __half2 p0 = __floats2half2_rn(v.x, v.y);
    __half2 p1 = __floats2half2_rn(v.z, v.w);
    hi[0] = *(uint32_t*)&p0;
    hi[1] = *(uint32_t*)&p1;
}

__global__ void __launch_bounds__(NTHR, 1)
hmma_head(const float* __restrict__ x,  const float* __restrict__ b1,
          const float* __restrict__ gamma, const float* __restrict__ beta,
          const float* __restrict__ Wout, const float* __restrict__ bout,
          float* __restrict__ out) {
    extern __shared__ char sm[];
    const uint32_t sbase = smem_u32(sm);
    const int tid  = threadIdx.x;
    const int lane = tid & 31;
    const int wid  = tid >> 5;         // 0..15
    const int wm   = wid & 3;          // 4 M-warps (16 rows each)
    const int wn   = wid >> 2;         // 4 N-warps (128 cols each)
    const int rowbase = blockIdx.x * MT;

    float* bgb = (float*)sm;           // b1[512] gamma[512] beta[512]
    for (int i = tid; i < 512; i += NTHR) {
        bgb[i]        = b1[i];
        bgb[512 + i]  = gamma[i];
        bgb[1024 + i] = beta[i];
    }

    // A-load duty: row ar (64 rows, 8 threads/row), 4-float quarter aq
    const int ar = tid >> 3, aq = tid & 7;
    const int arg = rowbase + ar;
    const float* xrow = x + (((size_t)((arg >> 9) * 513 + (arg & 511))) << 9) + aq * 4;

    // ---- prologue: chunk 0 into stage 0 ----
    {
        float4 xa = *(const float4*)(xrow);
        uint32_t hi[2];
        cvh4(xa, hi);
        *(uint2*)(sm + STAGE0 + AH_OFF + ar * STR + aq * 8) = *(uint2*)hi;
#pragma unroll
        for (int it = 0; it < 4; ++it) {
            int idx = tid + it * NTHR;
            int row = idx >> 2, q = idx & 3;
            cp16(sbase + STAGE0 + BH_OFF + row * STR + q * 16, g_W1h + row * 512 + q * 8);
        }
        asm volatile("cp.async.commit_group;");
        asm volatile("cp.async.wait_group 0;");
        __syncthreads();
    }

    float acc[16][4];
#pragma unroll
    for (int j = 0; j < 16; ++j)
#pragma unroll
        for (int e = 0; e < 4; ++e) acc[j][e] = 0.f;

    const uint32_t aoff  = (uint32_t)((lane & 15) * STR + (lane >> 4) * 16) + wm * 16 * STR;
    // B ldsm4: m0/m1 = n-rows 0-7 (k0-7, k8-15); m2/m3 = n-rows 8-15
    const uint32_t b4off = (uint32_t)((lane & 7) * STR + ((lane >> 3) & 1) * 16
                                      + (lane >> 4) * 8 * STR) + wn * 128 * STR;

#pragma unroll 1
    for (int c = 0; c < NCH; ++c) {
        const uint32_t stg  = STAGE0 + (uint32_t)(c & 1) * STG_SZ;
        const uint32_t nstg = STAGE0 + (uint32_t)((c & 1) ^ 1) * STG_SZ;
        float4 nxa;
        if (c < NCH - 1) {
            const int k0n = (c + 1) * KC;
            nxa = *(const float4*)(xrow + k0n);
#pragma unroll
            for (int it = 0; it < 4; ++it) {
                int idx = tid + it * NTHR;
                int row = idx >> 2, q = idx & 3;
                cp16(sbase + nstg + BH_OFF + row * STR + q * 16,
                     g_W1h + row * 512 + k0n + q * 8);
            }
            asm volatile("cp.async.commit_group;");
        }

        // ---- compute on stg: single product xh * Wh ----
#pragma unroll
        for (int ks = 0; ks < 2; ++ks) {
            uint32_t ah[4];
            const uint32_t ab = sbase + stg + aoff + ks * 32;
            ldsm4(ah, ab + AH_OFF);

            const uint32_t bb = sbase + stg + b4off + ks * 32 + BH_OFF;
            uint32_t bf[2][4];
            ldsm4(bf[0], bb);
#pragma unroll
            for (int jj = 0; jj < 8; ++jj) {
                const int cur = jj & 1, nxt = cur ^ 1;
                if (jj < 7) ldsm4(bf[nxt], bb + (uint32_t)(jj + 1) * (16 * STR));
                mma16816(acc[2*jj],   ah, &bf[cur][0]);
                mma16816(acc[2*jj+1], ah, &bf[cur][2]);
            }
        }

        if (c < NCH - 1) {
            uint32_t hi[2];
            cvh4(nxa, hi);
            *(uint2*)(sm + nstg + AH_OFF + ar * STR + aq * 8) = *(uint2*)hi;
        }
        asm volatile("cp.async.wait_group 0;");
        __syncthreads();
    }

    // ---- fused epilogue ----
    float2* stats = (float2*)(sm + STAGE0);          // [4][64]
    float2* munrs = (float2*)(sm + STAGE0 + 2048);   // [64]
    float*  pp    = (float*)(sm + STAGE0 + 2560);    // [4][64]

    // rows this warp covers: r = wm*16 + half*8 + (lane>>2)
#pragma unroll
    for (int half = 0; half < 2; ++half) {
        float s = 0.f, ss = 0.f;
#pragma unroll
        for (int j = 0; j < 16; ++j) {
            const int cc = wn * 128 + j * 8 + (lane & 3) * 2;
            float h0 = acc[j][half * 2 + 0] + bgb[cc];
            float h1 = acc[j][half * 2 + 1] + bgb[cc + 1];
            s += h0 + h1;
            ss += h0 * h0 + h1 * h1;
        }
        s  += __shfl_xor_sync(0xffffffffu, s, 1);  s  += __shfl_xor_sync(0xffffffffu, s, 2);
        ss += __shfl_xor_sync(0xffffffffu, ss, 1); ss += __shfl_xor_sync(0xffffffffu, ss, 2);
        if ((lane & 3) == 0) {
            const int r = wm * 16 + half * 8 + (lane >> 2);
            stats[wn * 64 + r] = make_float2(s, ss);
        }
    }
    __syncthreads();
    if (tid < 64) {
        float s = 0.f, ss = 0.f;
#pragma unroll
        for (int w = 0; w < 4; ++w) { float2 v = stats[w * 64 + tid]; s += v.x; ss += v.y; }
        const float mu = s * (1.f / 512.f);
        const float var = ss * (1.f / 512.f) - mu * mu;
        munrs[tid] = make_float2(mu, rsqrtf(var + 1e-5f));
    }
    __syncthreads();

#pragma unroll
    for (int half = 0; half < 2; ++half) {
        const int r = wm * 16 + half * 8 + (lane >> 2);
        const float2 mr = munrs[r];
        const int tt = (rowbase + r) & 511;
        const float* wrow = Wout + (((size_t)tt) << 9);
        float p = 0.f;
#pragma unroll
        for (int j = 0; j < 16; ++j) {
            const int cc = wn * 128 + j * 8 + (lane & 3) * 2;
            const float2 wo = *(const float2*)(wrow + cc);
            float h0 = acc[j][half * 2 + 0] + bgb[cc];
            float h1 = acc[j][half * 2 + 1] + bgb[cc + 1];
            float y0 = fmaxf((h0 - mr.x) * mr.y * bgb[512 + cc]     + bgb[1024 + cc],     0.f);
            float y1 = fmaxf((h1 - mr.x) * mr.y * bgb[512 + cc + 1] + bgb[1024 + cc + 1], 0.f);
            p += y0 * wo.x + y1 * wo.y;
        }
        p += __shfl_xor_sync(0xffffffffu, p, 1);
        p += __shfl_xor_sync(0xffffffffu, p, 2);
        if ((lane & 3) == 0) pp[wn * 64 + r] = p;
    }
    __syncthreads();
    if (tid < 64) {
        const int rg = rowbase + tid;
        const int tt = rg & 511;
        out[rg] = pp[tid] + pp[64 + tid] + pp[128 + tid] + pp[192 + tid] + bout[tt];
    }
}

extern "C" void kernel_launch(void* const* d_in, const int* in_sizes, int n_in,
                              void* d_out, int out_size) {
    const float* x     = (const float*)d_in[0];
    const float* W1    = (const float*)d_in[1];
    const float* b1    = (const float*)d_in[2];
    const float* gamma = (const float*)d_in[3];
    const float* beta  = (const float*)d_in[4];
    const float* Wout  = (const float*)d_in[5];
    const float* bout  = (const float*)d_in[6];
    float* out = (float*)d_out;

    cudaFuncSetAttribute(hmma_head, cudaFuncAttributeMaxDynamicSharedMemorySize, SMEM_TOTAL);

    split_w_kernel<<<1024, 256>>>(W1);
    hmma_head<<<131072 / MT, NTHR, SMEM_TOTAL>>>(x, b1, gamma, beta, Wout, bout, out);
}

// round 17
// speedup vs baseline: 1.6632x; 1.3430x over previous
#include <cuda_runtime.h>
#include <cuda_fp16.h>
#include <cstdint>

#define KC      64              // k elems per chunk
#define NCH     8               // 512 / 64
#define MT      64              // rows per CTA
#define NTHR    512
#define STR     144             // smem row stride bytes (64 fp16 = 128B + 16 pad)
#define AH_OFF  0               // A: 64*144  = 9216
#define BH_OFF  9216            // B: 512*144 = 73728
#define STG_SZ  82944
#define STAGE0  6144            // after b1/gamma/beta (1536 floats)
#define SMEM_TOTAL (STAGE0 + 2 * STG_SZ)

__device__ unsigned short g_W1h[512 * 512];

__global__ void split_w_kernel(const float* __restrict__ W1) {
    int i = blockIdx.x * 256 + threadIdx.x;
    g_W1h[i] = __half_as_ushort(__float2half_rn(W1[i]));
}

__device__ __forceinline__ uint32_t smem_u32(const void* p) {
    uint32_t a;
    asm("{ .reg .u64 t; cvta.to.shared.u64 t, %1; cvt.u32.u64 %0, t; }" : "=r"(a) : "l"(p));
    return a;
}
__device__ __forceinline__ void ldsm4(uint32_t* r, uint32_t a) {
    asm volatile("ldmatrix.sync.aligned.m8n8.x4.shared.b16 {%0,%1,%2,%3}, [%4];"
                 : "=r"(r[0]), "=r"(r[1]), "=r"(r[2]), "=r"(r[3]) : "r"(a));
}
__device__ __forceinline__ void mma16816(float* c, const uint32_t* a, const uint32_t* b) {
    asm volatile("mma.sync.aligned.m16n8k16.row.col.f32.f16.f16.f32 "
                 "{%0,%1,%2,%3}, {%4,%5,%6,%7}, {%8,%9}, {%0,%1,%2,%3};"
                 : "+f"(c[0]), "+f"(c[1]), "+f"(c[2]), "+f"(c[3])
                 : "r"(a[0]), "r"(a[1]), "r"(a[2]), "r"(a[3]), "r"(b[0]), "r"(b[1]));
}
__device__ __forceinline__ void cp16(uint32_t dst, const void* src) {
    asm volatile("cp.async.ca.shared.global [%0], [%1], 16;"
                 :: "r"(dst), "l"(__cvta_generic_to_global(src)));
}
// convert 8 floats to 4 packed fp16 pairs
__device__ __forceinline__ void cvh8(const float4& a, const float4& b, uint32_t* o) {
    __half2 p0 = __floats2half2_rn(a.x, a.y);
    __half2 p1 = __floats2half2_rn(a.z, a.w);
    __half2 p2 = __floats2half2_rn(b.x, b.y);
    __half2 p3 = __floats2half2_rn(b.z, b.w);
    o[0] = *(uint32_t*)&p0; o[1] = *(uint32_t*)&p1;
    o[2] = *(uint32_t*)&p2; o[3] = *(uint32_t*)&p3;
}

__global__ void __launch_bounds__(NTHR, 1)
hmma_head(const float* __restrict__ x,  const float* __restrict__ b1,
          const float* __restrict__ gamma, const float* __restrict__ beta,
          const float* __restrict__ Wout, const float* __restrict__ bout,
          float* __restrict__ out) {
    extern __shared__ char sm[];
    const uint32_t sbase = smem_u32(sm);
    const int tid  = threadIdx.x;
    const int lane = tid & 31;
    const int wid  = tid >> 5;         // 0..15
    const int wm   = wid & 1;          // 2 M-warps (32 rows each)
    const int wn   = wid >> 1;         // 8 N-warps (64 cols each)
    const int rowbase = blockIdx.x * MT;

    float* bgb = (float*)sm;           // b1[512] gamma[512] beta[512]
    for (int i = tid; i < 512; i += NTHR) {
        bgb[i]        = b1[i];
        bgb[512 + i]  = gamma[i];
        bgb[1024 + i] = beta[i];
    }

    // A-load duty: row ar (64 rows, 8 threads/row), 8-float chunk aq
    const int ar = tid >> 3, aq = tid & 7;
    const int arg = rowbase + ar;
    const float* xrow = x + (((size_t)((arg >> 9) * 513 + (arg & 511))) << 9) + aq * 8;

    // ---- prologue: chunk 0 into stage 0 ----
    {
        float4 xa = *(const float4*)(xrow);
        float4 xb = *(const float4*)(xrow + 4);
        uint32_t h[4];
        cvh8(xa, xb, h);
        *(uint4*)(sm + STAGE0 + AH_OFF + ar * STR + aq * 16) = *(uint4*)h;
#pragma unroll
        for (int it = 0; it < 8; ++it) {
            int idx = tid + it * NTHR;
            int row = idx >> 3, q = idx & 7;
            cp16(sbase + STAGE0 + BH_OFF + row * STR + q * 16, g_W1h + row * 512 + q * 8);
        }
        asm volatile("cp.async.commit_group;");
        asm volatile("cp.async.wait_group 0;");
        __syncthreads();
    }

    float acc[2][8][4];
#pragma unroll
    for (int i = 0; i < 2; ++i)
#pragma unroll
        for (int j = 0; j < 8; ++j)
#pragma unroll
            for (int e = 0; e < 4; ++e) acc[i][j][e] = 0.f;

    const uint32_t aoff  = (uint32_t)((lane & 15) * STR + (lane >> 4) * 16) + wm * 32 * STR;
    // B ldsm4: m0/m1 = n-rows 0-7 (k0-7, k8-15); m2/m3 = n-rows 8-15
    const uint32_t b4off = (uint32_t)((lane & 7) * STR + ((lane >> 3) & 1) * 16
                                      + (lane >> 4) * 8 * STR) + wn * 64 * STR;

#pragma unroll 1
    for (int c = 0; c < NCH; ++c) {
        const uint32_t stg  = STAGE0 + (uint32_t)(c & 1) * STG_SZ;
        const uint32_t nstg = STAGE0 + (uint32_t)((c & 1) ^ 1) * STG_SZ;
        float4 nxa, nxb;
        if (c < NCH - 1) {
            const int k0n = (c + 1) * KC;
            nxa = *(const float4*)(xrow + k0n);
            nxb = *(const float4*)(xrow + k0n + 4);
#pragma unroll
            for (int it = 0; it < 8; ++it) {
                int idx = tid + it * NTHR;
                int row = idx >> 3, q = idx & 7;
                cp16(sbase + nstg + BH_OFF + row * STR + q * 16,
                     g_W1h + row * 512 + k0n + q * 8);
            }
            asm volatile("cp.async.commit_group;");
        }

        // ---- compute on stg: 4 k-steps of 16 ----
#pragma unroll
        for (int ks = 0; ks < 4; ++ks) {
            uint32_t a0[4], a1[4];
            const uint32_t ab = sbase + stg + aoff + ks * 32;
            ldsm4(a0, ab + AH_OFF);
            ldsm4(a1, ab + AH_OFF + 16 * STR);

            const uint32_t bb = sbase + stg + b4off + ks * 32 + BH_OFF;
            uint32_t bf[2][4];
            ldsm4(bf[0], bb);
#pragma unroll
            for (int jj = 0; jj < 4; ++jj) {
                const int cur = jj & 1, nxt = cur ^ 1;
                if (jj < 3) ldsm4(bf[nxt], bb + (uint32_t)(jj + 1) * (16 * STR));
                mma16816(acc[0][2*jj],   a0, &bf[cur][0]);
                mma16816(acc[1][2*jj],   a1, &bf[cur][0]);
                mma16816(acc[0][2*jj+1], a0, &bf[cur][2]);
                mma16816(acc[1][2*jj+1], a1, &bf[cur][2]);
            }
        }

        if (c < NCH - 1) {
            uint32_t h[4];
            cvh8(nxa, nxb, h);
            *(uint4*)(sm + nstg + AH_OFF + ar * STR + aq * 16) = *(uint4*)h;
        }
        asm volatile("cp.async.wait_group 0;");
        __syncthreads();
    }

    // ---- fused epilogue ----
    float2* stats = (float2*)(sm + STAGE0);          // [8][64]
    float2* munrs = (float2*)(sm + STAGE0 + 4096);   // [64]
    float*  pp    = (float*)(sm + STAGE0 + 4608);    // [8][64]

    // rows this thread covers: r = wm*32 + i*16 + half*8 + (lane>>2)
#pragma unroll
    for (int i = 0; i < 2; ++i)
#pragma unroll
    for (int half = 0; half < 2; ++half) {
        float s = 0.f, ss = 0.f;
#pragma unroll
        for (int j = 0; j < 8; ++j) {
            const int cc = wn * 64 + j * 8 + (lane & 3) * 2;
            float h0 = acc[i][j][half * 2 + 0] + bgb[cc];
            float h1 = acc[i][j][half * 2 + 1] + bgb[cc + 1];
            s += h0 + h1;
            ss += h0 * h0 + h1 * h1;
        }
        s  += __shfl_xor_sync(0xffffffffu, s, 1);  s  += __shfl_xor_sync(0xffffffffu, s, 2);
        ss += __shfl_xor_sync(0xffffffffu, ss, 1); ss += __shfl_xor_sync(0xffffffffu, ss, 2);
        if ((lane & 3) == 0) {
            const int r = wm * 32 + i * 16 + half * 8 + (lane >> 2);
            stats[wn * 64 + r] = make_float2(s, ss);
        }
    }
    __syncthreads();
    if (tid < 64) {
        float s = 0.f, ss = 0.f;
#pragma unroll
        for (int w = 0; w < 8; ++w) { float2 v = stats[w * 64 + tid]; s += v.x; ss += v.y; }
        const float mu = s * (1.f / 512.f);
        const float var = ss * (1.f / 512.f) - mu * mu;
        munrs[tid] = make_float2(mu, rsqrtf(var + 1e-5f));
    }
    __syncthreads();

#pragma unroll
    for (int i = 0; i < 2; ++i)
#pragma unroll
    for (int half = 0; half < 2; ++half) {
        const int r = wm * 32 + i * 16 + half * 8 + (lane >> 2);
        const float2 mr = munrs[r];
        const int tt = (rowbase + r) & 511;
        const float* wrow = Wout + (((size_t)tt) << 9);
        float p = 0.f;
#pragma unroll
        for (int j = 0; j < 8; ++j) {
            const int cc = wn * 64 + j * 8 + (lane & 3) * 2;
            const float2 wo = *(const float2*)(wrow + cc);
            float h0 = acc[i][j][half * 2 + 0] + bgb[cc];
            float h1 = acc[i][j][half * 2 + 1] + bgb[cc + 1];
            float y0 = fmaxf((h0 - mr.x) * mr.y * bgb[512 + cc]     + bgb[1024 + cc],     0.f);
            float y1 = fmaxf((h1 - mr.x) * mr.y * bgb[512 + cc + 1] + bgb[1024 + cc + 1], 0.f);
            p += y0 * wo.x + y1 * wo.y;
        }
        p += __shfl_xor_sync(0xffffffffu, p, 1);
        p += __shfl_xor_sync(0xffffffffu, p, 2);
        if ((lane & 3) == 0) pp[wn * 64 + r] = p;
    }
    __syncthreads();
    if (tid < 64) {
        const int rg = rowbase + tid;
        const int tt = rg & 511;
        float p = 0.f;
#pragma unroll
        for (int w = 0; w < 8; ++w) p += pp[w * 64 + tid];
        out[rg] = p + bout[tt];
    }
}

extern "C" void kernel_launch(void* const* d_in, const int* in_sizes, int n_in,
                              void* d_out, int out_size) {
    const float* x     = (const float*)d_in[0];
    const float* W1    = (const float*)d_in[1];
    const float* b1    = (const float*)d_in[2];
    const float* gamma = (const float*)d_in[3];
    const float* beta  = (const float*)d_in[4];
    const float* Wout  = (const float*)d_in[5];
    const float* bout  = (const float*)d_in[6];
    float* out = (float*)d_out;

    cudaFuncSetAttribute(hmma_head, cudaFuncAttributeMaxDynamicSharedMemorySize, SMEM_TOTAL);

    split_w_kernel<<<1024, 256>>>(W1);
    hmma_head<<<131072 / MT, NTHR, SMEM_TOTAL>>>(x, b1, gamma, beta, Wout, bout, out);
}